// round 7
// baseline (speedup 1.0000x reference)
#include <cuda_runtime.h>

#define NB   8
#define NC   6
#define HH   512
#define WW   512
#define HW   (HH * WW)           // 262144
#define NPIX (NB * HW)           // 2097152

#define ETH  16                  // edge strip height (full 512-wide rows)
#define SS   528                 // smem column stride; image col c stored at c+8

#define LOSS_BLOCKS ((NPIX / 4) / 256)   // 2048

#define L2E  1.4426950408889634f  // log2(e)
#define LN2  0.6931471805599453   // ln(2), applied once in finalize

// Global accumulators (log2-domain sums). Statically zero; loss kernel's
// last block resets them so every graph replay starts from zero.
__device__ double       g_A = 0.0;   // sum lp2 over all pixels
__device__ double       g_B = 0.0;   // sum S2  over edge pixels
__device__ double       g_C = 0.0;   // sum lp2 over edge pixels
__device__ unsigned int g_count = 0u;
__device__ unsigned int g_done  = 0u;
__device__ __align__(16) unsigned char g_pack[NPIX];  // label | (edge << 3)

__device__ __forceinline__ float ex2f(float v) {
    float r; asm("ex2.approx.f32 %0, %1;" : "=f"(r) : "f"(v)); return r;
}
__device__ __forceinline__ float lg2f(float v) {
    float r; asm("lg2.approx.f32 %0, %1;" : "=f"(r) : "f"(v)); return r;
}
__device__ __forceinline__ void cp16(unsigned int dst, const void* src) {
    asm volatile("cp.async.cg.shared.global [%0], [%1], 16;"
                 :: "r"(dst), "l"(src));
}
__device__ __forceinline__ void cp4(unsigned int dst, const void* src) {
    asm volatile("cp.async.ca.shared.global [%0], [%1], 4;"
                 :: "r"(dst), "l"(src));
}

// ---------------------------------------------------------------------------
// Kernel 1: full-width strip, exact integer 11x11 box sum, packed byte out.
// ---------------------------------------------------------------------------
__global__ void __launch_bounds__(512)
edge_pack_kernel(const int* __restrict__ target) {
    __shared__ unsigned char  t_s[(ETH + 10) * SS];   // 26*528 = 13728 B
    __shared__ unsigned short csum_s[ETH * SS];       // 16*528*2 = 16896 B

    const int tid = threadIdx.x;
    const int y0  = blockIdx.x * ETH;
    const int b   = blockIdx.y;
    const int* tb = target + b * HW;

    // Zero both arrays (guard columns / out-of-image rows must read as 0)
    {
        uint4* p1 = reinterpret_cast<uint4*>(t_s);      // 13728/16 = 858
        for (int i = tid; i < 858; i += 512) p1[i] = make_uint4(0, 0, 0, 0);
        uint4* p2 = reinterpret_cast<uint4*>(csum_s);   // 16896/16 = 1056
        for (int i = tid; i < 1056; i += 512) p2[i] = make_uint4(0, 0, 0, 0);
    }
    __syncthreads();

    // Phase 1: load rows y0-5 .. y0+20 (clamped) as bytes; col c at pos c+8
#pragma unroll
    for (int r = 0; r < ETH + 10; r++) {
        const int gy = y0 + r - 5;
        if (gy >= 0 && gy < HH)
            t_s[r * SS + tid + 8] = (unsigned char)tb[gy * WW + tid];
    }
    __syncthreads();

    // Phase 2: vertical sliding 11-sums; one column per thread
    {
        const int pos = tid + 8;
        int s = 0;
#pragma unroll
        for (int i = 0; i < 11; i++) s += t_s[i * SS + pos];
        csum_s[pos] = (unsigned short)s;
#pragma unroll
        for (int r = 1; r < ETH; r++) {
            s += (int)t_s[(r + 10) * SS + pos] - (int)t_s[(r - 1) * SS + pos];
            csum_s[r * SS + pos] = (unsigned short)s;
        }
    }
    __syncthreads();

    // Phase 3: 16 rows x 32 lanes; each thread 16 consecutive pixels.
    {
        const int r  = tid >> 5;          // 0..15
        const int xs = (tid & 31) * 16;   // 0,16,...,496

        unsigned int w[16];
        {
            const uint4* src = reinterpret_cast<const uint4*>(&csum_s[r * SS + xs]);
            uint4 u0 = src[0], u1 = src[1], u2 = src[2], u3 = src[3];
            w[0]=u0.x; w[1]=u0.y; w[2]=u0.z; w[3]=u0.w;
            w[4]=u1.x; w[5]=u1.y; w[6]=u1.z; w[7]=u1.w;
            w[8]=u2.x; w[9]=u2.y; w[10]=u2.z; w[11]=u2.w;
            w[12]=u3.x; w[13]=u3.y; w[14]=u3.z; w[15]=u3.w;
        }
#define CS(L) ((int)((w[(L) >> 1] >> (((L) & 1) * 16)) & 0xFFFFu))

        unsigned int lw[4];
        {
            const uint2* lp0 = reinterpret_cast<const uint2*>(
                &t_s[(r + 5) * SS + xs + 8]);
            uint2 l0 = lp0[0], l1 = lp0[1];
            lw[0] = l0.x; lw[1] = l0.y; lw[2] = l1.x; lw[3] = l1.y;
        }

        int s = 0;
#pragma unroll
        for (int d = 0; d < 11; d++) s += CS(3 + d);

        unsigned int out[4] = {0u, 0u, 0u, 0u};
#pragma unroll
        for (int k = 0; k < 16; k++) {
            if (k) s += CS(k + 13) - CS(k + 2);
            const int lab = (int)((lw[k >> 2] >> (8 * (k & 3))) & 0xFFu);
            const unsigned int e = (121 * lab != s) ? 1u : 0u;
            out[k >> 2] |= ((unsigned int)lab | (e << 3)) << (8 * (k & 3));
        }
#undef CS
        *reinterpret_cast<uint4*>(&g_pack[b * HW + (y0 + r) * WW + xs]) =
            make_uint4(out[0], out[1], out[2], out[3]);
    }
}

// ---------------------------------------------------------------------------
// Kernel 2: streaming loss. cp.async stages all per-thread data in smem
// (loads never occupy registers -> low regs, high occupancy, guaranteed
// MLP=7 per thread). Each thread consumes only its own staged bytes, so
// wait_group 0 suffices (no barrier). Log2-domain math, 4 px/thread.
// ---------------------------------------------------------------------------
__global__ void __launch_bounds__(256)
loss_kernel(const float* __restrict__ x, float* __restrict__ out) {
    __shared__ __align__(16) float xs_s[NC * 1024];   // [c][tid*4] : 24 KB
    __shared__ unsigned int  pk_s[256];               // 1 KB

    const int tid = threadIdx.x;
    const int t4 = blockIdx.x * blockDim.x + tid;     // 0 .. NPIX/4-1
    const int p0 = t4 * 4;
    const int b  = p0 >> 18;         // / HW
    const int hw = p0 & (HW - 1);

    const float4* xb = reinterpret_cast<const float4*>(
        x + (size_t)b * NC * HW + hw);

    // Stage: 6 x 16B (L1-bypass) + 4B pack, all in flight at once
    const unsigned int s_x  = (unsigned int)__cvta_generic_to_shared(xs_s)
                              + tid * 16u;
    const unsigned int s_pk = (unsigned int)__cvta_generic_to_shared(pk_s)
                              + tid * 4u;
#pragma unroll
    for (int c = 0; c < NC; c++)
        cp16(s_x + c * 4096u, xb + c * (HW / 4));
    cp4(s_pk, g_pack + p0);
    asm volatile("cp.async.commit_group;");
    asm volatile("cp.async.wait_group 0;");

    const unsigned int pk = pk_s[tid];
    const int lab0 = (int)( pk        & 7u), e0 = (int)((pk >> 3)  & 1u);
    const int lab1 = (int)((pk >> 8)  & 7u), e1 = (int)((pk >> 11) & 1u);
    const int lab2 = (int)((pk >> 16) & 7u), e2 = (int)((pk >> 19) & 1u);
    const int lab3 = (int)((pk >> 24) & 7u), e3 = (int)((pk >> 27) & 1u);

    float es0 = 0.f, es1 = 0.f, es2 = 0.f, es3 = 0.f;   // sum 2^(x*log2e)
    float T0  = 0.f, T1  = 0.f, T2  = 0.f, T3  = 0.f;   // sum x
    float xl0 = 0.f, xl1 = 0.f, xl2 = 0.f, xl3 = 0.f;   // x at label

#pragma unroll
    for (int c = 0; c < NC; c++) {
        const float4 f = *reinterpret_cast<const float4*>(
            &xs_s[c * 1024 + tid * 4]);
        es0 += ex2f(f.x * L2E);
        es1 += ex2f(f.y * L2E);
        es2 += ex2f(f.z * L2E);
        es3 += ex2f(f.w * L2E);
        T0 += f.x;  T1 += f.y;  T2 += f.z;  T3 += f.w;
        xl0 = (lab0 == c) ? f.x : xl0;
        xl1 = (lab1 == c) ? f.y : xl1;
        xl2 = (lab2 == c) ? f.z : xl2;
        xl3 = (lab3 == c) ? f.w : xl3;
    }

    // Per-pixel epilogue in log2 domain
    const float l0 = lg2f(es0), l1 = lg2f(es1), l2 = lg2f(es2), l3 = lg2f(es3);
    const float lp0 = fmaf(xl0, L2E, -l0);
    const float lp1 = fmaf(xl1, L2E, -l1);
    const float lp2 = fmaf(xl2, L2E, -l2);
    const float lp3 = fmaf(xl3, L2E, -l3);
    const float S0 = fmaf(l0, -6.0f, T0 * L2E);
    const float S1 = fmaf(l1, -6.0f, T1 * L2E);
    const float S2 = fmaf(l2, -6.0f, T2 * L2E);
    const float S3 = fmaf(l3, -6.0f, T3 * L2E);
    const float f0 = (float)e0, f1 = (float)e1, f2 = (float)e2, f3 = (float)e3;

    float accA = (lp0 + lp1) + (lp2 + lp3);
    float accB = fmaf(f0, S0,  fmaf(f1, S1,  fmaf(f2, S2,  f3 * S3)));
    float accC = fmaf(f0, lp0, fmaf(f1, lp1, fmaf(f2, lp2, f3 * lp3)));
    int   accN = (e0 + e1) + (e2 + e3);

    // Block reduction, then 4 global atomics
#pragma unroll
    for (int off = 16; off; off >>= 1) {
        accA += __shfl_down_sync(0xffffffffu, accA, off);
        accB += __shfl_down_sync(0xffffffffu, accB, off);
        accC += __shfl_down_sync(0xffffffffu, accC, off);
        accN += __shfl_down_sync(0xffffffffu, accN, off);
    }
    __shared__ float red[3 * 8];
    __shared__ int   redn[8];
    __shared__ bool  is_last;
    const int lane = tid & 31, w = tid >> 5;
    if (lane == 0) { red[w] = accA; red[8 + w] = accB; red[16 + w] = accC; redn[w] = accN; }
    __syncthreads();
    if (tid < 8) {
        float a = red[tid], bb = red[8 + tid], c = red[16 + tid];
        int   n = redn[tid];
#pragma unroll
        for (int off = 4; off; off >>= 1) {
            a  += __shfl_down_sync(0x000000ffu, a, off);
            bb += __shfl_down_sync(0x000000ffu, bb, off);
            c  += __shfl_down_sync(0x000000ffu, c, off);
            n  += __shfl_down_sync(0x000000ffu, n, off);
        }
        if (tid == 0) {
            atomicAdd(&g_A, (double)a);
            atomicAdd(&g_B, (double)bb);
            atomicAdd(&g_C, (double)c);
            atomicAdd(&g_count, (unsigned int)n);
        }
    }

    // Last-block finalize: scalar math, output, reset
    if (tid == 0) {
        __threadfence();
        const unsigned int prev = atomicAdd(&g_done, 1u);
        is_last = (prev == (unsigned int)(LOSS_BLOCKS - 1));
    }
    __syncthreads();
    if (is_last && tid == 0) {
        const double A = atomicAdd(&g_A, 0.0);
        const double B = atomicAdd(&g_B, 0.0);
        const double C = atomicAdd(&g_C, 0.0);
        const unsigned int cnt = atomicAdd(&g_count, 0u);

        const double s  = fmin((double)cnt / (double)NPIX, 0.2);
        const double cl = 1.0 - 2.0 * s + s / 6.0;
        const double total = LN2 * (A + s * B + (cl - 1.0) * C);
        out[0] = (float)(-(total / (double)NPIX));

        g_A = 0.0; g_B = 0.0; g_C = 0.0;
        g_count = 0u; g_done = 0u;
    }
}

extern "C" void kernel_launch(void* const* d_in, const int* in_sizes, int n_in,
                              void* d_out, int out_size) {
    const float* x      = (const float*)d_in[0];
    const int*   target = (const int*)d_in[1];
    float*       out    = (float*)d_out;

    dim3 eg(HH / ETH, NB);            // (32, 8) = 256 blocks x 512 threads
    edge_pack_kernel<<<eg, 512>>>(target);

    loss_kernel<<<LOSS_BLOCKS, 256>>>(x, out);
}